// round 6
// baseline (speedup 1.0000x reference)
#include <cuda_runtime.h>
#include <cuda_bf16.h>

#define B_ 4
#define N_ 512
#define D_ 128
#define H_ 128

typedef unsigned long long ull;

// ---- packed f32x2 helpers -------------------------------------------------
__device__ __forceinline__ void fma2(ull &a, ull x, ull w) {
    asm("fma.rn.f32x2 %0, %1, %2, %0;" : "+l"(a) : "l"(x), "l"(w));
}
__device__ __forceinline__ ull add2(ull a, ull b) {
    ull r; asm("add.rn.f32x2 %0, %1, %2;" : "=l"(r) : "l"(a), "l"(b)); return r;
}
__device__ __forceinline__ ull pack2(float lo, float hi) {
    ull r; asm("mov.b64 %0, {%1, %2};" : "=l"(r) : "f"(lo), "f"(hi)); return r;
}
__device__ __forceinline__ void unpack2(ull v, float &lo, float &hi) {
    asm("mov.b64 {%0, %1}, %2;" : "=f"(lo), "=f"(hi) : "l"(v));
}
__device__ __forceinline__ float hadd2(ull v) { float lo, hi; unpack2(v, lo, hi); return lo + hi; }
__device__ __forceinline__ ull relu2(ull v) {
    float lo, hi; unpack2(v, lo, hi);
    return pack2(fmaxf(lo, 0.f), fmaxf(hi, 0.f));
}

__device__ __forceinline__ void cp_async16(void* smem_dst, const void* gsrc) {
    unsigned s = (unsigned)__cvta_generic_to_shared(smem_dst);
    asm volatile("cp.async.cg.shared.global [%0], [%1], 16;" :: "r"(s), "l"(gsrc));
}

// ---- scratch --------------------------------------------------------------
__device__ float gA[B_ * N_ * H_];
__device__ float gC[B_ * N_ * H_];
__device__ float gDiag[B_ * N_];

// ---------------------------------------------------------------------------
// Precompute: 8 rows/block, 256 threads = h(128) x row-group(2) of 4 rows.
// W streamed through smem with cp.async double buffering:
// 16 chunks x 8 d-rows = full D=128.
// ---------------------------------------------------------------------------
#define RW 8
#define NCHUNK 16

__global__ __launch_bounds__(256) void precompute_kernel(
    const float* __restrict__ X,
    const float* __restrict__ W1c, const float* __restrict__ b1c,
    const float* __restrict__ W1s, const float* __restrict__ b1s,
    const float* __restrict__ W2s, const float* __restrict__ b2s)
{
    const int tid = threadIdx.x;
    const int h   = tid & 127;
    const int rg  = tid >> 7;              // row group 0/1 (4 rows each)
    const int blockRow = blockIdx.x * RW;

    __shared__ float xs[RW][D_];                  // 4 KB
    __shared__ float wsm[2][3][8][H_];            // 24 KB: [buf][mat][d-row][h]
    __shared__ float red[RW][4];

    // load 8 X rows
    {
        const float4* src = (const float4*)(X + (size_t)blockRow * D_);
        float4* dst = (float4*)&xs[0][0];
        for (int k = tid; k < RW * D_ / 4; k += 256) dst[k] = src[k];
    }

    const int q   = tid >> 5;    // d-row within chunk 0..7
    const int seg = tid & 31;    // float4 within row

    // stage chunk 0
    {
        cp_async16(&wsm[0][0][q][seg * 4], W1c + (size_t)q * H_ + seg * 4);
        cp_async16(&wsm[0][1][q][seg * 4], W1c + (size_t)(D_ + q) * H_ + seg * 4);
        cp_async16(&wsm[0][2][q][seg * 4], W1s + (size_t)q * H_ + seg * 4);
        asm volatile("cp.async.commit_group;");
    }

    ull accA[4], accC[4], accS[4];
#pragma unroll
    for (int r = 0; r < 4; r++) { accA[r] = 0ull; accC[r] = 0ull; accS[r] = 0ull; }

    for (int c = 0; c < NCHUNK; c++) {
        if (c < NCHUNK - 1) {
            const int nb = (c + 1) & 1;
            const int d0 = (c + 1) * 8 + q;
            cp_async16(&wsm[nb][0][q][seg * 4], W1c + (size_t)d0 * H_ + seg * 4);
            cp_async16(&wsm[nb][1][q][seg * 4], W1c + (size_t)(D_ + d0) * H_ + seg * 4);
            cp_async16(&wsm[nb][2][q][seg * 4], W1s + (size_t)d0 * H_ + seg * 4);
            asm volatile("cp.async.commit_group;");
            asm volatile("cp.async.wait_group 1;");
        } else {
            asm volatile("cp.async.wait_group 0;");
        }
        __syncthreads();

        const int buf = c & 1;
#pragma unroll
        for (int dd = 0; dd < 4; dd++) {
            const ull wa = pack2(wsm[buf][0][2 * dd][h], wsm[buf][0][2 * dd + 1][h]);
            const ull wc = pack2(wsm[buf][1][2 * dd][h], wsm[buf][1][2 * dd + 1][h]);
            const ull ws = pack2(wsm[buf][2][2 * dd][h], wsm[buf][2][2 * dd + 1][h]);
            const int dGlob = c * 8 + dd * 2;
#pragma unroll
            for (int r = 0; r < 4; r++) {
                const ull xv = *(const ull*)&xs[rg * 4 + r][dGlob];
                fma2(accA[r], xv, wa);
                fma2(accC[r], xv, wc);
                fma2(accS[r], xv, ws);
            }
        }
        __syncthreads();
    }

    // epilogue
    const float bc = b1c[h];
    const float bs = b1s[h];
    const float w2 = W2s[h];
    const int warp = tid >> 5;
#pragma unroll
    for (int r = 0; r < 4; r++) {
        const int row = blockRow + rg * 4 + r;
        gA[(size_t)row * H_ + h] = hadd2(accA[r]);
        gC[(size_t)row * H_ + h] = hadd2(accC[r]) + bc;
        float t = fmaxf(hadd2(accS[r]) + bs, 0.f) * w2;
#pragma unroll
        for (int off = 16; off > 0; off >>= 1)
            t += __shfl_down_sync(0xffffffffu, t, off);
        if ((tid & 31) == 0) red[rg * 4 + r][warp & 3] = t;
    }
    __syncthreads();
    if (tid < RW) {
        const float s = red[tid][0] + red[tid][1] + red[tid][2] + red[tid][3] + b2s[0];
        gDiag[blockRow + tid] = 1.f / (1.f + __expf(-s));
    }
}

// ---------------------------------------------------------------------------
// Pair kernel v5: 16x16 tile, 64 threads, 2x2 micro-tile over FULL h=128.
// No inter-thread reduction, single sync. Grid (32,32,B), lower tiles exit.
// ---------------------------------------------------------------------------
__global__ __launch_bounds__(64) void pair_kernel(
    const float* __restrict__ W2c, const float* __restrict__ b2c,
    float* __restrict__ out)
{
    const int ti = blockIdx.x, tj = blockIdx.y, b = blockIdx.z;
    if (tj < ti) return;

    __shared__ float As[16][132];
    __shared__ float Cs[16][132];
    __shared__ float St[16][17];
    __shared__ float ws[H_];

    const int tid = threadIdx.x;
    const int i0 = ti * 16, j0 = tj * 16;

    // loads: 16 rows x 32 float4 each matrix
    {
        const float4* ga4 = (const float4*)(gA + ((size_t)b * N_ + i0) * H_);
        const float4* gc4 = (const float4*)(gC + ((size_t)b * N_ + j0) * H_);
#pragma unroll
        for (int k = 0; k < 8; k++) {
            const int e = k * 64 + tid;
            const int r = e >> 5, c = e & 31;
            ((float4*)&As[r][0])[c] = ga4[r * 32 + c];
            ((float4*)&Cs[r][0])[c] = gc4[r * 32 + c];
        }
        ws[tid] = W2c[tid];
        ws[tid + 64] = W2c[tid + 64];
    }
    __syncthreads();

    const int ty = tid >> 3;     // rows ty, ty+8
    const int tx = tid & 7;      // cols tx, tx+8

    ull a00 = 0ull, a01 = 0ull, a10 = 0ull, a11 = 0ull;

#pragma unroll 8
    for (int hh = 0; hh < H_; hh += 4) {
        const ulonglong2 av0 = *(const ulonglong2*)&As[ty][hh];
        const ulonglong2 av1 = *(const ulonglong2*)&As[ty + 8][hh];
        const ulonglong2 cv0 = *(const ulonglong2*)&Cs[tx][hh];
        const ulonglong2 cv1 = *(const ulonglong2*)&Cs[tx + 8][hh];
        const ulonglong2 wv  = *(const ulonglong2*)&ws[hh];

        fma2(a00, relu2(add2(av0.x, cv0.x)), wv.x);
        fma2(a00, relu2(add2(av0.y, cv0.y)), wv.y);
        fma2(a01, relu2(add2(av0.x, cv1.x)), wv.x);
        fma2(a01, relu2(add2(av0.y, cv1.y)), wv.y);
        fma2(a10, relu2(add2(av1.x, cv0.x)), wv.x);
        fma2(a10, relu2(add2(av1.y, cv0.y)), wv.y);
        fma2(a11, relu2(add2(av1.x, cv1.x)), wv.x);
        fma2(a11, relu2(add2(av1.y, cv1.y)), wv.y);
    }

    const float bb = b2c[0];
    const float s00 = 1.f / (1.f + __expf(-(hadd2(a00) + bb)));
    const float s01 = 1.f / (1.f + __expf(-(hadd2(a01) + bb)));
    const float s10 = 1.f / (1.f + __expf(-(hadd2(a10) + bb)));
    const float s11 = 1.f / (1.f + __expf(-(hadd2(a11) + bb)));

    if (ti != tj) {
        St[ty][tx]         = s00;
        St[ty][tx + 8]     = s01;
        St[ty + 8][tx]     = s10;
        St[ty + 8][tx + 8] = s11;
        __syncthreads();

        const int r = tid >> 2, c = (tid & 3) * 4;
        float4 v = make_float4(St[r][c], St[r][c + 1], St[r][c + 2], St[r][c + 3]);
        *(float4*)&out[((size_t)b * N_ + i0 + r) * N_ + j0 + c] = v;
        float4 vt = make_float4(St[c][r], St[c + 1][r], St[c + 2][r], St[c + 3][r]);
        *(float4*)&out[((size_t)b * N_ + j0 + r) * N_ + i0 + c] = vt;
    } else {
        const int gi0 = b * N_ + i0;
        const float sv[2][2] = {{s00, s01}, {s10, s11}};
#pragma unroll
        for (int k = 0; k < 2; k++) {
#pragma unroll
            for (int m = 0; m < 2; m++) {
                const int i = ty + 8 * k, j = tx + 8 * m;
                if (i < j)       { St[i][j] = sv[k][m]; St[j][i] = sv[k][m]; }
                else if (i == j) { St[i][i] = gDiag[gi0 + i]; }
            }
        }
        __syncthreads();
        const int r = tid >> 2, c = (tid & 3) * 4;
        float4 v = make_float4(St[r][c], St[r][c + 1], St[r][c + 2], St[r][c + 3]);
        *(float4*)&out[((size_t)b * N_ + i0 + r) * N_ + j0 + c] = v;
    }
}

// ---------------------------------------------------------------------------
extern "C" void kernel_launch(void* const* d_in, const int* in_sizes, int n_in,
                              void* d_out, int out_size)
{
    const float* X   = (const float*)d_in[0];
    const float* W1c = (const float*)d_in[1];
    const float* b1c = (const float*)d_in[2];
    const float* W2c = (const float*)d_in[3];
    const float* b2c = (const float*)d_in[4];
    const float* W1s = (const float*)d_in[5];
    const float* b1s = (const float*)d_in[6];
    const float* W2s = (const float*)d_in[7];
    const float* b2s = (const float*)d_in[8];
    float* out = (float*)d_out;

    precompute_kernel<<<(B_ * N_) / RW, 256>>>(X, W1c, b1c, W1s, b1s, W2s, b2s);

    dim3 grid(N_ / 16, N_ / 16, B_);
    pair_kernel<<<grid, 64>>>(W2c, b2c, out);
}